// round 2
// baseline (speedup 1.0000x reference)
#include <cuda_runtime.h>
#include <math.h>

// Problem constants
#define R_TOT 49152   // B*M*NVIEW = 32*256*6
#define BMR   8192    // B*M
#define EMB   1024
#define HID   256
#define NV    6

// ---------------- scratch (static __device__ globals; no runtime alloc) ----
// g_big serves two non-overlapping lifetimes:
//   phase 1: stage-A output y [49152,1024]   (consumed by stage B)
//   phase 2: per-layer input-gate precompute gx [49152,1024]
__device__ float g_big[(size_t)R_TOT * EMB];
__device__ float g_x0[(size_t)R_TOT * HID];       // LSTM seq buffer ping
__device__ float g_x1[(size_t)R_TOT * HID];       // LSTM seq buffer pong
__device__ float g_gates[(size_t)BMR * 4 * HID];  // per-step gates [8192,1024]
__device__ float g_h[(size_t)BMR * HID];
__device__ float g_c[(size_t)BMR * HID];
__device__ float g_score[BMR];

// ---------------- tiled fp32 SGEMM, NT layout (A[M,K] row-major, B[N,K] row-major) ---
// C[m,n] = sum_k A[m,k]*B[n,k]  + epilogue per MODE.
// MODE 0: C = resid + gelu_exact(acc + bias[n])
// MODE 1: C = acc + bias[n] (+ bias2[n] if non-null)
// MODE 2: C = acc + addend[m*add_stride + n]
// All dims are multiples of 128 / 8 here, so no bounds checks.
#define GBM 128
#define GBN 128
#define GBK 8
#define GTM 8
#define GTN 8

template <int MODE>
__global__ void __launch_bounds__(256, 2)
sgemm_nt(const float* __restrict__ A, const float* __restrict__ B,
         float* __restrict__ C, int M, int N, int K,
         const float* __restrict__ bias, const float* __restrict__ bias2,
         const float* __restrict__ addend, int add_stride,
         const float* __restrict__ resid)
{
    __shared__ float As[GBK][GBM];
    __shared__ float Bs[GBK][GBN];

    const int bm = blockIdx.y * GBM;
    const int bn = blockIdx.x * GBN;
    const int tid = threadIdx.x;

    // Each thread loads one float4 of A and one of B per k-tile.
    const int lrow = tid >> 1;        // 0..127
    const int lcol = (tid & 1) * 4;   // 0 or 4
    const float* Aptr = A + (size_t)(bm + lrow) * K + lcol;
    const float* Bptr = B + (size_t)(bn + lrow) * K + lcol;

    const int ty = tid >> 4;          // 0..15 -> row group
    const int tx = tid & 15;          // 0..15 -> col group

    float acc[GTM][GTN];
#pragma unroll
    for (int i = 0; i < GTM; i++)
#pragma unroll
        for (int j = 0; j < GTN; j++) acc[i][j] = 0.f;

    for (int k0 = 0; k0 < K; k0 += GBK) {
        float4 av = *(const float4*)(Aptr + k0);
        float4 bv = *(const float4*)(Bptr + k0);
        As[lcol + 0][lrow] = av.x;
        As[lcol + 1][lrow] = av.y;
        As[lcol + 2][lrow] = av.z;
        As[lcol + 3][lrow] = av.w;
        Bs[lcol + 0][lrow] = bv.x;
        Bs[lcol + 1][lrow] = bv.y;
        Bs[lcol + 2][lrow] = bv.z;
        Bs[lcol + 3][lrow] = bv.w;
        __syncthreads();

#pragma unroll
        for (int k = 0; k < GBK; k++) {
            float4 a0 = *(const float4*)&As[k][ty * GTM];
            float4 a1 = *(const float4*)&As[k][ty * GTM + 4];
            float4 b0 = *(const float4*)&Bs[k][tx * GTN];
            float4 b1 = *(const float4*)&Bs[k][tx * GTN + 4];
            float af[GTM] = {a0.x, a0.y, a0.z, a0.w, a1.x, a1.y, a1.z, a1.w};
            float bf[GTN] = {b0.x, b0.y, b0.z, b0.w, b1.x, b1.y, b1.z, b1.w};
#pragma unroll
            for (int i = 0; i < GTM; i++)
#pragma unroll
                for (int j = 0; j < GTN; j++)
                    acc[i][j] = fmaf(af[i], bf[j], acc[i][j]);
        }
        __syncthreads();
    }

#pragma unroll
    for (int i = 0; i < GTM; i++) {
        const int row = bm + ty * GTM + i;
#pragma unroll
        for (int j = 0; j < GTN; j++) {
            const int col = bn + tx * GTN + j;
            float v = acc[i][j];
            if (MODE == 0) {
                v += bias[col];
                v = 0.5f * v * (1.0f + erff(v * 0.70710678118654752f));
                v += resid[(size_t)row * N + col];
            } else if (MODE == 1) {
                v += bias[col];
                if (bias2) v += bias2[col];
            } else {
                v += addend[(size_t)row * add_stride + col];
            }
            C[(size_t)row * N + col] = v;
        }
    }
}

// ---------------- LSTM cell (gate order i,f,g,o) -------------------------
__global__ void lstm_cell(const float* __restrict__ gates, int gstride, int first,
                          float* __restrict__ h, float* __restrict__ c,
                          float* __restrict__ outseq, int t)
{
    int idx = blockIdx.x * blockDim.x + threadIdx.x;   // over BMR*HID
    int bmi = idx >> 8;
    int j = idx & (HID - 1);
    const float* g = gates + (size_t)bmi * gstride;
    float ig = g[j];
    float fg = g[HID + j];
    float gg = g[2 * HID + j];
    float og = g[3 * HID + j];
    float cp = first ? 0.f : c[idx];
    float si = 1.f / (1.f + expf(-ig));
    float sf = 1.f / (1.f + expf(-fg));
    float so = 1.f / (1.f + expf(-og));
    float cn = sf * cp + si * tanhf(gg);
    float hn = so * tanhf(cn);
    c[idx] = cn;
    h[idx] = hn;
    outseq[((size_t)bmi * NV + t) * HID + j] = hn;
}

// ---------------- folded scoring head ------------------------------------
// score[bm] = sum_n Ws[n] * (Wv . h[bm,n,:])
__global__ void score_kernel(const float* __restrict__ hseq,
                             const float* __restrict__ Wv,
                             const float* __restrict__ Ws,
                             float* __restrict__ score)
{
    int bm = blockIdx.x;
    int t = threadIdx.x;   // 256 = HID
    float acc = 0.f;
#pragma unroll
    for (int n = 0; n < NV; n++)
        acc += Ws[n] * hseq[((size_t)bm * NV + n) * HID + t];
    acc *= Wv[t];
    __shared__ float red[256];
    red[t] = acc;
    __syncthreads();
    for (int s = 128; s > 0; s >>= 1) {
        if (t < s) red[t] += red[t + s];
        __syncthreads();
    }
    if (t == 0) score[bm] = red[0];
}

// out[b] = mean_m score[b*256+m] + bv*sum(Ws) + bs
__global__ void final_kernel(const float* __restrict__ score,
                             const float* __restrict__ Ws,
                             const float* __restrict__ bv,
                             const float* __restrict__ bs,
                             float* __restrict__ out)
{
    int b = blockIdx.x;
    int t = threadIdx.x;   // 256 = M
    __shared__ float red[256];
    red[t] = score[b * 256 + t];
    __syncthreads();
    for (int s = 128; s > 0; s >>= 1) {
        if (t < s) red[t] += red[t + s];
        __syncthreads();
    }
    if (t == 0) {
        float sws = 0.f;
        for (int n = 0; n < NV; n++) sws += Ws[n];
        out[b] = red[0] * (1.0f / 256.0f) + bv[0] * sws + bs[0];
    }
}

// ---------------- launch -------------------------------------------------
extern "C" void kernel_launch(void* const* d_in, const int* in_sizes, int n_in,
                              void* d_out, int out_size)
{
    const float* swin = (const float*)d_in[0];
    const float* conv = (const float*)d_in[1];
    const float* Wc   = (const float*)d_in[2];
    const float* bc   = (const float*)d_in[3];
    const float* Win  = (const float*)d_in[4];
    const float* b_in = (const float*)d_in[5];
    const float* Wih  = (const float*)d_in[6];
    const float* Whh  = (const float*)d_in[7];
    const float* bih  = (const float*)d_in[8];
    const float* bhh  = (const float*)d_in[9];
    const float* Wv   = (const float*)d_in[10];
    const float* bv   = (const float*)d_in[11];
    const float* Ws   = (const float*)d_in[12];
    const float* bs   = (const float*)d_in[13];
    float* out = (float*)d_out;

    float *big, *x0, *x1, *gates, *h, *c, *score;
    cudaGetSymbolAddress((void**)&big, g_big);
    cudaGetSymbolAddress((void**)&x0, g_x0);
    cudaGetSymbolAddress((void**)&x1, g_x1);
    cudaGetSymbolAddress((void**)&gates, g_gates);
    cudaGetSymbolAddress((void**)&h, g_h);
    cudaGetSymbolAddress((void**)&c, g_c);
    cudaGetSymbolAddress((void**)&score, g_score);

    float* y  = big;   // phase-1 lifetime
    float* gx = big;   // phase-2 lifetime (starts after stage B has consumed y)

    // Stage A: y = swin + gelu(conv @ Wc^T + bc)        [49152,1024] K=1024
    sgemm_nt<0><<<dim3(EMB / GBN, R_TOT / GBM), 256>>>(
        conv, Wc, y, R_TOT, EMB, EMB, bc, nullptr, nullptr, 0, swin);

    // Stage B: x0 = y @ Win^T + b_in                    [49152,256]  K=1024
    sgemm_nt<1><<<dim3(HID / GBN, R_TOT / GBM), 256>>>(
        y, Win, x0, R_TOT, HID, EMB, b_in, nullptr, nullptr, 0, nullptr);

    float* bufs[2] = {x0, x1};
    for (int l = 0; l < 3; l++) {
        const float* in = bufs[l & 1];
        float* outb = bufs[(l & 1) ^ 1];

        // Input-gate precompute: gx = in @ Wih[l]^T + bih[l] + bhh[l]   [49152,1024] K=256
        sgemm_nt<1><<<dim3(4 * HID / GBN, R_TOT / GBM), 256>>>(
            in, Wih + (size_t)l * 4 * HID * HID, gx, R_TOT, 4 * HID, HID,
            bih + l * 4 * HID, bhh + l * 4 * HID, nullptr, 0, nullptr);

        // t = 0: h0 = c0 = 0 -> gates come straight from gx (row stride NV*1024)
        lstm_cell<<<(BMR * HID) / 256, 256>>>(gx, NV * 4 * HID, 1, h, c, outb, 0);

        for (int t = 1; t < NV; t++) {
            // gates = h @ Whh[l]^T + gx[:, t, :]                       [8192,1024] K=256
            sgemm_nt<2><<<dim3(4 * HID / GBN, BMR / GBM), 256>>>(
                h, Whh + (size_t)l * 4 * HID * HID, gates, BMR, 4 * HID, HID,
                nullptr, nullptr, gx + (size_t)t * 4 * HID, NV * 4 * HID, nullptr);
            lstm_cell<<<(BMR * HID) / 256, 256>>>(gates, 4 * HID, 0, h, c, outb, t);
        }
    }

    // After 3 layers (x0->x1->x0->x1), final hidden sequence is in x1.
    score_kernel<<<BMR, 256>>>(x1, Wv, Ws, score);
    final_kernel<<<32, 256>>>(score, Ws, bv, bs, out);
}

// round 3
// speedup vs baseline: 2.7255x; 2.7255x over previous
#include <cuda_runtime.h>
#include <math.h>
#include <stdint.h>

// Problem constants
#define R_TOT 49152   // B*M*NVIEW = 32*256*6
#define BMR   8192    // B*M
#define EMB   1024
#define HID   256
#define NV    6

// ---------------- scratch (static __device__ globals; no runtime alloc) ----
__device__ float g_big[(size_t)R_TOT * EMB];      // y (phase1) / gx (phase2)
__device__ float g_x0[(size_t)R_TOT * HID];
__device__ float g_x1[(size_t)R_TOT * HID];
__device__ float g_gates[(size_t)BMR * 4 * HID];
__device__ float g_h[(size_t)BMR * HID];
__device__ float g_c[(size_t)BMR * HID];
__device__ float g_score[BMR];

// ---------------- tf32 helpers -------------------------------------------
__device__ __forceinline__ uint32_t f2tf(float f) {
    uint32_t r;
    asm("cvt.rna.tf32.f32 %0, %1;" : "=r"(r) : "f"(f));
    return r;
}

#define SROW 20   // padded smem row stride in floats (conflict-free ldmatrix)

// ---------------- tensor-core tf32 GEMM, NT layout ------------------------
// C[m,n] = sum_k A[m,k]*B[n,k] + epilogue per MODE (same modes as before).
// Block tile 128x128, k-tile 16, 8 warps (2x4), warp tile 64x32.
template <int MODE>
__global__ void __launch_bounds__(256, 2)
tgemm_nt(const float* __restrict__ A, const float* __restrict__ B,
         float* __restrict__ C, int M, int N, int K,
         const float* __restrict__ bias, const float* __restrict__ bias2,
         const float* __restrict__ addend, int add_stride,
         const float* __restrict__ resid)
{
    __shared__ __align__(16) float As[2][128 * SROW];
    __shared__ __align__(16) float Bs[2][128 * SROW];

    const int tid  = threadIdx.x;
    const int w    = tid >> 5;
    const int lane = tid & 31;
    const int wr   = w >> 2;    // warp row (0..1) -> 64 m each
    const int wc   = w & 3;     // warp col (0..3) -> 32 n each
    const int bm = blockIdx.y * 128;
    const int bn = blockIdx.x * 128;

    // ---- gmem loader mapping: thread -> (row, k-half) --------------------
    const int lrow = tid >> 1;         // 0..127
    const int lk   = (tid & 1) * 8;    // 0 or 8
    const float* Ap = A + (size_t)(bm + lrow) * K + lk;
    const float* Bp = B + (size_t)(bn + lrow) * K + lk;
    const int s_off = lrow * SROW + lk;

    // ---- ldmatrix per-lane offsets (floats, relative to stage base) ------
    // A tiles (x4): t0=(r0-7,k0-3) t1=(r8-15,k0-3) t2=(r0-7,k4-7) t3=(r8-15,k4-7)
    const int a_r8 = ((lane >> 3) & 1) * 8;
    const int a_k4 = ((lane >> 4) & 1) * 4;
    const int a_off0 = (wr * 64 + (lane & 7) + a_r8) * SROW + a_k4;
    // B tiles (x4): t0=(n0-7,k0-3) t1=(n0-7,k4-7) t2=(n8-15,k0-3) t3=(n8-15,k4-7)
    const int b_k4 = ((lane >> 3) & 1) * 4;
    const int b_n8 = ((lane >> 4) & 1) * 8;
    const int b_off0 = (wc * 32 + (lane & 7) + b_n8) * SROW + b_k4;

    const uint32_t As_s = (uint32_t)__cvta_generic_to_shared(&As[0][0]);
    const uint32_t Bs_s = (uint32_t)__cvta_generic_to_shared(&Bs[0][0]);

    float acc[4][4][4];   // [mtile][ntile][c0..c3]
#pragma unroll
    for (int i = 0; i < 4; i++)
#pragma unroll
        for (int j = 0; j < 4; j++)
#pragma unroll
            for (int q = 0; q < 4; q++) acc[i][j][q] = 0.f;

    const int T = K >> 4;
    float4 pa0, pa1, pb0, pb1;

    // preload tile 0
    pa0 = *(const float4*)(Ap);
    pa1 = *(const float4*)(Ap + 4);
    pb0 = *(const float4*)(Bp);
    pb1 = *(const float4*)(Bp + 4);
    {
        uint4 u;
        u.x = f2tf(pa0.x); u.y = f2tf(pa0.y); u.z = f2tf(pa0.z); u.w = f2tf(pa0.w);
        *(uint4*)&As[0][s_off] = u;
        u.x = f2tf(pa1.x); u.y = f2tf(pa1.y); u.z = f2tf(pa1.z); u.w = f2tf(pa1.w);
        *(uint4*)&As[0][s_off + 4] = u;
        u.x = f2tf(pb0.x); u.y = f2tf(pb0.y); u.z = f2tf(pb0.z); u.w = f2tf(pb0.w);
        *(uint4*)&Bs[0][s_off] = u;
        u.x = f2tf(pb1.x); u.y = f2tf(pb1.y); u.z = f2tf(pb1.z); u.w = f2tf(pb1.w);
        *(uint4*)&Bs[0][s_off + 4] = u;
    }
    __syncthreads();

    int st = 0;
    for (int t = 0; t < T; ++t) {
        if (t + 1 < T) {
            const float* Ap2 = Ap + (t + 1) * 16;
            const float* Bp2 = Bp + (t + 1) * 16;
            pa0 = *(const float4*)(Ap2);
            pa1 = *(const float4*)(Ap2 + 4);
            pb0 = *(const float4*)(Bp2);
            pb1 = *(const float4*)(Bp2 + 4);
        }

#pragma unroll
        for (int ks = 0; ks < 2; ++ks) {
            uint32_t a[4][4], b[4][2];
#pragma unroll
            for (int mt = 0; mt < 4; mt++) {
                uint32_t addr = As_s + (uint32_t)(st * 128 * SROW + a_off0 + mt * 16 * SROW + ks * 8) * 4u;
                asm volatile("ldmatrix.sync.aligned.m8n8.x4.shared.b16 {%0,%1,%2,%3}, [%4];"
                             : "=r"(a[mt][0]), "=r"(a[mt][1]), "=r"(a[mt][2]), "=r"(a[mt][3])
                             : "r"(addr));
            }
#pragma unroll
            for (int p = 0; p < 2; p++) {
                uint32_t addr = Bs_s + (uint32_t)(st * 128 * SROW + b_off0 + p * 16 * SROW + ks * 8) * 4u;
                uint32_t r0, r1, r2, r3;
                asm volatile("ldmatrix.sync.aligned.m8n8.x4.shared.b16 {%0,%1,%2,%3}, [%4];"
                             : "=r"(r0), "=r"(r1), "=r"(r2), "=r"(r3)
                             : "r"(addr));
                b[2 * p][0] = r0; b[2 * p][1] = r1;
                b[2 * p + 1][0] = r2; b[2 * p + 1][1] = r3;
            }
#pragma unroll
            for (int mt = 0; mt < 4; mt++)
#pragma unroll
                for (int nt = 0; nt < 4; nt++)
                    asm volatile(
                        "mma.sync.aligned.m16n8k8.row.col.f32.tf32.tf32.f32 "
                        "{%0,%1,%2,%3}, {%4,%5,%6,%7}, {%8,%9}, {%0,%1,%2,%3};"
                        : "+f"(acc[mt][nt][0]), "+f"(acc[mt][nt][1]),
                          "+f"(acc[mt][nt][2]), "+f"(acc[mt][nt][3])
                        : "r"(a[mt][0]), "r"(a[mt][1]), "r"(a[mt][2]), "r"(a[mt][3]),
                          "r"(b[nt][0]), "r"(b[nt][1]));
        }

        if (t + 1 < T) {
            const int so = (st ^ 1) * 128 * SROW + s_off;
            uint4 u;
            u.x = f2tf(pa0.x); u.y = f2tf(pa0.y); u.z = f2tf(pa0.z); u.w = f2tf(pa0.w);
            *(uint4*)&As[0][so] = u;
            u.x = f2tf(pa1.x); u.y = f2tf(pa1.y); u.z = f2tf(pa1.z); u.w = f2tf(pa1.w);
            *(uint4*)&As[0][so + 4] = u;
            u.x = f2tf(pb0.x); u.y = f2tf(pb0.y); u.z = f2tf(pb0.z); u.w = f2tf(pb0.w);
            *(uint4*)&Bs[0][so] = u;
            u.x = f2tf(pb1.x); u.y = f2tf(pb1.y); u.z = f2tf(pb1.z); u.w = f2tf(pb1.w);
            *(uint4*)&Bs[0][so + 4] = u;
        }
        __syncthreads();
        st ^= 1;
    }

    // ---- epilogue --------------------------------------------------------
    const int g  = lane >> 2;
    const int lq = lane & 3;
#pragma unroll
    for (int mt = 0; mt < 4; mt++) {
#pragma unroll
        for (int nt = 0; nt < 4; nt++) {
            const int col = bn + wc * 32 + nt * 8 + 2 * lq;
#pragma unroll
            for (int half = 0; half < 2; half++) {   // c0,c1 then c2,c3 (row +8)
                const int row = bm + wr * 64 + mt * 16 + g + half * 8;
                float v0 = acc[mt][nt][half * 2 + 0];
                float v1 = acc[mt][nt][half * 2 + 1];
                if (MODE == 0) {
                    v0 += bias[col];
                    v1 += bias[col + 1];
                    v0 = 0.5f * v0 * (1.0f + erff(v0 * 0.70710678118654752f));
                    v1 = 0.5f * v1 * (1.0f + erff(v1 * 0.70710678118654752f));
                    const float2 r = *(const float2*)&resid[(size_t)row * N + col];
                    v0 += r.x; v1 += r.y;
                } else if (MODE == 1) {
                    v0 += bias[col];
                    v1 += bias[col + 1];
                    if (bias2) { v0 += bias2[col]; v1 += bias2[col + 1]; }
                } else {
                    const float2 ad = *(const float2*)&addend[(size_t)row * add_stride + col];
                    v0 += ad.x; v1 += ad.y;
                }
                float2 o; o.x = v0; o.y = v1;
                *(float2*)&C[(size_t)row * N + col] = o;
            }
        }
    }
}

// ---------------- LSTM cell (gate order i,f,g,o) -------------------------
__global__ void lstm_cell(const float* __restrict__ gates, int gstride, int first,
                          float* __restrict__ h, float* __restrict__ c,
                          float* __restrict__ outseq, int t)
{
    int idx = blockIdx.x * blockDim.x + threadIdx.x;
    int bmi = idx >> 8;
    int j = idx & (HID - 1);
    const float* g = gates + (size_t)bmi * gstride;
    float ig = g[j];
    float fg = g[HID + j];
    float gg = g[2 * HID + j];
    float og = g[3 * HID + j];
    float cp = first ? 0.f : c[idx];
    float si = 1.f / (1.f + expf(-ig));
    float sf = 1.f / (1.f + expf(-fg));
    float so = 1.f / (1.f + expf(-og));
    float cn = sf * cp + si * tanhf(gg);
    float hn = so * tanhf(cn);
    c[idx] = cn;
    h[idx] = hn;
    outseq[((size_t)bmi * NV + t) * HID + j] = hn;
}

// ---------------- folded scoring head ------------------------------------
__global__ void score_kernel(const float* __restrict__ hseq,
                             const float* __restrict__ Wv,
                             const float* __restrict__ Ws,
                             float* __restrict__ score)
{
    int bm = blockIdx.x;
    int t = threadIdx.x;
    float acc = 0.f;
#pragma unroll
    for (int n = 0; n < NV; n++)
        acc += Ws[n] * hseq[((size_t)bm * NV + n) * HID + t];
    acc *= Wv[t];
    __shared__ float red[256];
    red[t] = acc;
    __syncthreads();
    for (int s = 128; s > 0; s >>= 1) {
        if (t < s) red[t] += red[t + s];
        __syncthreads();
    }
    if (t == 0) score[bm] = red[0];
}

__global__ void final_kernel(const float* __restrict__ score,
                             const float* __restrict__ Ws,
                             const float* __restrict__ bv,
                             const float* __restrict__ bs,
                             float* __restrict__ out)
{
    int b = blockIdx.x;
    int t = threadIdx.x;
    __shared__ float red[256];
    red[t] = score[b * 256 + t];
    __syncthreads();
    for (int s = 128; s > 0; s >>= 1) {
        if (t < s) red[t] += red[t + s];
        __syncthreads();
    }
    if (t == 0) {
        float sws = 0.f;
        for (int n = 0; n < NV; n++) sws += Ws[n];
        out[b] = red[0] * (1.0f / 256.0f) + bv[0] * sws + bs[0];
    }
}

// ---------------- launch -------------------------------------------------
extern "C" void kernel_launch(void* const* d_in, const int* in_sizes, int n_in,
                              void* d_out, int out_size)
{
    const float* swin = (const float*)d_in[0];
    const float* conv = (const float*)d_in[1];
    const float* Wc   = (const float*)d_in[2];
    const float* bc   = (const float*)d_in[3];
    const float* Win  = (const float*)d_in[4];
    const float* b_in = (const float*)d_in[5];
    const float* Wih  = (const float*)d_in[6];
    const float* Whh  = (const float*)d_in[7];
    const float* bih  = (const float*)d_in[8];
    const float* bhh  = (const float*)d_in[9];
    const float* Wv   = (const float*)d_in[10];
    const float* bv   = (const float*)d_in[11];
    const float* Ws   = (const float*)d_in[12];
    const float* bs   = (const float*)d_in[13];
    float* out = (float*)d_out;

    float *big, *x0, *x1, *gates, *h, *c, *score;
    cudaGetSymbolAddress((void**)&big, g_big);
    cudaGetSymbolAddress((void**)&x0, g_x0);
    cudaGetSymbolAddress((void**)&x1, g_x1);
    cudaGetSymbolAddress((void**)&gates, g_gates);
    cudaGetSymbolAddress((void**)&h, g_h);
    cudaGetSymbolAddress((void**)&c, g_c);
    cudaGetSymbolAddress((void**)&score, g_score);

    float* y  = big;   // phase-1 lifetime
    float* gx = big;   // phase-2 lifetime

    // Stage A: y = swin + gelu(conv @ Wc^T + bc)        [49152,1024] K=1024
    tgemm_nt<0><<<dim3(EMB / 128, R_TOT / 128), 256>>>(
        conv, Wc, y, R_TOT, EMB, EMB, bc, nullptr, nullptr, 0, swin);

    // Stage B: x0 = y @ Win^T + b_in                    [49152,256]  K=1024
    tgemm_nt<1><<<dim3(HID / 128, R_TOT / 128), 256>>>(
        y, Win, x0, R_TOT, HID, EMB, b_in, nullptr, nullptr, 0, nullptr);

    float* bufs[2] = {x0, x1};
    for (int l = 0; l < 3; l++) {
        const float* in = bufs[l & 1];
        float* outb = bufs[(l & 1) ^ 1];

        // gx = in @ Wih[l]^T + bih[l] + bhh[l]          [49152,1024] K=256
        tgemm_nt<1><<<dim3(4 * HID / 128, R_TOT / 128), 256>>>(
            in, Wih + (size_t)l * 4 * HID * HID, gx, R_TOT, 4 * HID, HID,
            bih + l * 4 * HID, bhh + l * 4 * HID, nullptr, 0, nullptr);

        lstm_cell<<<(BMR * HID) / 256, 256>>>(gx, NV * 4 * HID, 1, h, c, outb, 0);

        for (int t = 1; t < NV; t++) {
            // gates = h @ Whh[l]^T + gx[:, t, :]        [8192,1024] K=256
            tgemm_nt<2><<<dim3(4 * HID / 128, BMR / 128), 256>>>(
                h, Whh + (size_t)l * 4 * HID * HID, gates, BMR, 4 * HID, HID,
                nullptr, nullptr, gx + (size_t)t * 4 * HID, NV * 4 * HID, nullptr);
            lstm_cell<<<(BMR * HID) / 256, 256>>>(gates, 4 * HID, 0, h, c, outb, t);
        }
    }

    score_kernel<<<BMR, 256>>>(x1, Wv, Ws, score);
    final_kernel<<<32, 256>>>(score, Ws, bv, bs, out);
}